// round 6
// baseline (speedup 1.0000x reference)
#include <cuda_runtime.h>
#include <cuda_bf16.h>
#include <cstdint>

#define N_NODES_MAX 100000
#define N_EDGES_MAX 1600000
#define N_GRAPHS_MAX 512

// ---------------- scratch (device globals; no allocation allowed) ----------
__device__ __align__(16) __nv_bfloat16 g_h0[N_NODES_MAX * 32];
__device__ __align__(16) __nv_bfloat16 g_h1[N_NODES_MAX * 64];
__device__ int   g_deg[N_NODES_MAX];
__device__ int   g_rowptr[N_NODES_MAX + 1];
__device__ int   g_wp[N_NODES_MAX];
__device__ int   g_src_sorted[N_EDGES_MAX];
__device__ int   g_bsum[1024];
__device__ int   g_boff[1024];
__device__ __align__(16) float g_gsum[N_GRAPHS_MAX * 64];
__device__ int   g_gcnt[N_GRAPHS_MAX];

__device__ __forceinline__ float2 bf2f(unsigned u) {
    __nv_bfloat162 b;
    *(unsigned*)&b = u;
    return __bfloat1622float2(b);
}
__device__ __forceinline__ unsigned f2bf(float a, float b) {
    __nv_bfloat162 v = __floats2bfloat162_rn(a, b);
    return *(unsigned*)&v;
}

// ---------------- degree count + graph node count ----------------------------
__global__ void degree_kernel(const int* __restrict__ dst,
                              const int* __restrict__ batch, int E, int n) {
    int i = blockIdx.x * blockDim.x + threadIdx.x;
    if (i < E) atomicAdd(&g_deg[dst[i]], 1);
    if (i < n) atomicAdd(&g_gcnt[batch[i]], 1);
}

// ---------------- multi-block scan, pass 1 -----------------------------------
__global__ void scan1_kernel(int n) {
    __shared__ int warpsums[32];
    int t = threadIdx.x, lane = t & 31, w = t >> 5;
    int i = blockIdx.x * 1024 + t;
    int v = (i < n) ? g_deg[i] : 0;
    int x = v;
    #pragma unroll
    for (int off = 1; off < 32; off <<= 1) {
        int u = __shfl_up_sync(0xFFFFFFFFu, x, off);
        if (lane >= off) x += u;
    }
    if (lane == 31) warpsums[w] = x;
    __syncthreads();
    if (w == 0) {
        int y = warpsums[lane];
        #pragma unroll
        for (int off = 1; off < 32; off <<= 1) {
            int u = __shfl_up_sync(0xFFFFFFFFu, y, off);
            if (lane >= off) y += u;
        }
        warpsums[lane] = y;
    }
    __syncthreads();
    int woff = (w > 0) ? warpsums[w - 1] : 0;
    if (i < n) g_rowptr[i] = x + woff - v;
    if (t == 0) g_bsum[blockIdx.x] = warpsums[31];
}

// ---------------- scan pass 2 -------------------------------------------------
__global__ void scan2_kernel(int nb, int n) {
    __shared__ int warpsums[32];
    int t = threadIdx.x, lane = t & 31, w = t >> 5;
    int v = (t < nb) ? g_bsum[t] : 0;
    int x = v;
    #pragma unroll
    for (int off = 1; off < 32; off <<= 1) {
        int u = __shfl_up_sync(0xFFFFFFFFu, x, off);
        if (lane >= off) x += u;
    }
    if (lane == 31) warpsums[w] = x;
    __syncthreads();
    if (w == 0) {
        int y = warpsums[lane];
        #pragma unroll
        for (int off = 1; off < 32; off <<= 1) {
            int u = __shfl_up_sync(0xFFFFFFFFu, y, off);
            if (lane >= off) y += u;
        }
        warpsums[lane] = y;
    }
    __syncthreads();
    int woff = (w > 0) ? warpsums[w - 1] : 0;
    if (t < nb) g_boff[t] = x + woff - v;
    if (t == 0) g_rowptr[n] = warpsums[31];
}

// ---------------- scan pass 3 -------------------------------------------------
__global__ void scan3_kernel(int n) {
    int i = blockIdx.x * blockDim.x + threadIdx.x;
    if (i < n) {
        int v = g_rowptr[i] + g_boff[i >> 10];
        g_rowptr[i] = v;
        g_wp[i] = v;
    }
}

// ---------------- bucket edges by dst ----------------------------------------
__global__ void bucket_kernel(const int* __restrict__ src,
                              const int* __restrict__ dst, int E) {
    int e = blockIdx.x * blockDim.x + threadIdx.x;
    if (e < E) {
        int d = dst[e];
        int p = atomicAdd(&g_wp[d], 1);
        g_src_sorted[p] = src[e];
    }
}

// ---------------- pre MLP: x[N,5] @ W[5,32] + b, relu -> bf16 ----------------
__global__ void pre_kernel(const float* __restrict__ x,
                           const float* __restrict__ w,
                           const float* __restrict__ b, int n) {
    int tid = blockIdx.x * blockDim.x + threadIdx.x;
    if (tid >= n * 32) return;
    int node = tid >> 5, j = tid & 31;
    const float* xr = x + node * 5;
    float acc = __ldg(&b[j]);
    #pragma unroll
    for (int k = 0; k < 5; k++) acc += xr[k] * __ldg(&w[k * 32 + j]);
    g_h0[tid] = __float2bfloat16(fmaxf(acc, 0.f));
}

// ================= conv1: persistent, 4 nodes/warp, fp32 weights =============
__global__ __launch_bounds__(256) void conv1_kernel(
    const float* __restrict__ wl, const float* __restrict__ bl,
    const float* __restrict__ wr, int n, int ntiles)
{
    __shared__ __align__(16) float4 sw[32 * 32];   // 16KB {wl[k][2l],wr[k][2l],wl[k][2l+1],wr[k][2l+1]}
    __shared__ float2 sA[8][4][32];                // 8KB (a, h)
    __shared__ int    s_idx[8][32];                // 1KB

    for (int i = threadIdx.x; i < 32 * 32; i += blockDim.x) {
        int k = i >> 5, o2 = (i & 31) * 2;
        sw[i] = make_float4(wl[k * 64 + o2],     wr[k * 64 + o2],
                            wl[k * 64 + o2 + 1], wr[k * 64 + o2 + 1]);
    }
    __syncthreads();

    int warp = threadIdx.x >> 5, lane = threadIdx.x & 31;
    float bias0 = __ldg(&bl[2 * lane]), bias1 = __ldg(&bl[2 * lane + 1]);

    for (int tile = blockIdx.x; tile < ntiles; tile += gridDim.x) {
        int nbase = tile * 32 + warp * 4;

        #pragma unroll
        for (int t = 0; t < 4; t++) {
            int node = nbase + t;
            float a = 0.f, h = 0.f;
            if (node < n) {
                int s0 = g_rowptr[node], s1 = g_rowptr[node + 1];
                for (int base = s0; base < s1; base += 32) {
                    int cnt = min(32, s1 - base);
                    __syncwarp();
                    if (base + lane < s1) s_idx[warp][lane] = g_src_sorted[base + lane];
                    __syncwarp();
                    int j = 0;
                    for (; j + 4 <= cnt; j += 4) {
                        int i0 = s_idx[warp][j],     i1 = s_idx[warp][j + 1];
                        int i2 = s_idx[warp][j + 2], i3 = s_idx[warp][j + 3];
                        float v0 = __bfloat162float(g_h0[i0 * 32 + lane]);
                        float v1 = __bfloat162float(g_h0[i1 * 32 + lane]);
                        float v2 = __bfloat162float(g_h0[i2 * 32 + lane]);
                        float v3 = __bfloat162float(g_h0[i3 * 32 + lane]);
                        a += (v0 + v1) + (v2 + v3);
                    }
                    for (; j < cnt; j++)
                        a += __bfloat162float(g_h0[s_idx[warp][j] * 32 + lane]);
                }
                int deg = s1 - s0;
                a *= (deg > 0) ? 1.f / (float)deg : 0.f;
                h = __bfloat162float(g_h0[node * 32 + lane]);
            }
            sA[warp][t][lane] = make_float2(a, h);
        }
        __syncwarp();

        float a00 = bias0, a01 = bias1, a10 = bias0, a11 = bias1;
        float a20 = bias0, a21 = bias1, a30 = bias0, a31 = bias1;
        #pragma unroll
        for (int k = 0; k < 32; k++) {
            float4 w = sw[k * 32 + lane];
            float2 A0 = sA[warp][0][k], A1 = sA[warp][1][k];
            float2 A2 = sA[warp][2][k], A3 = sA[warp][3][k];
            a00 += A0.x * w.x + A0.y * w.y;  a01 += A0.x * w.z + A0.y * w.w;
            a10 += A1.x * w.x + A1.y * w.y;  a11 += A1.x * w.z + A1.y * w.w;
            a20 += A2.x * w.x + A2.y * w.y;  a21 += A2.x * w.z + A2.y * w.w;
            a30 += A3.x * w.x + A3.y * w.y;  a31 += A3.x * w.z + A3.y * w.w;
        }

        float s0_ = a00 * a00 + a01 * a01;
        float s1_ = a10 * a10 + a11 * a11;
        float s2_ = a20 * a20 + a21 * a21;
        float s3_ = a30 * a30 + a31 * a31;
        #pragma unroll
        for (int off = 16; off; off >>= 1) {
            s0_ += __shfl_xor_sync(0xFFFFFFFFu, s0_, off);
            s1_ += __shfl_xor_sync(0xFFFFFFFFu, s1_, off);
            s2_ += __shfl_xor_sync(0xFFFFFFFFu, s2_, off);
            s3_ += __shfl_xor_sync(0xFFFFFFFFu, s3_, off);
        }
        float i0 = 1.f / fmaxf(sqrtf(s0_), 1e-12f);
        float i1 = 1.f / fmaxf(sqrtf(s1_), 1e-12f);
        float i2 = 1.f / fmaxf(sqrtf(s2_), 1e-12f);
        float i3 = 1.f / fmaxf(sqrtf(s3_), 1e-12f);
        unsigned* o = (unsigned*)g_h1;
        if (nbase + 0 < n) o[(nbase + 0) * 32 + lane] = f2bf(fmaxf(a00 * i0, 0.f), fmaxf(a01 * i0, 0.f));
        if (nbase + 1 < n) o[(nbase + 1) * 32 + lane] = f2bf(fmaxf(a10 * i1, 0.f), fmaxf(a11 * i1, 0.f));
        if (nbase + 2 < n) o[(nbase + 2) * 32 + lane] = f2bf(fmaxf(a20 * i2, 0.f), fmaxf(a21 * i2, 0.f));
        if (nbase + 3 < n) o[(nbase + 3) * 32 + lane] = f2bf(fmaxf(a30 * i3, 0.f), fmaxf(a31 * i3, 0.f));
    }
}

// ===== conv2 + fused pool: persistent, 6 nodes/warp, fp32 weights ===========
// staging: uint2 { bf16x2(ax,ay), raw bf16x2 H-bits } per (t, k-pair-lane)
__global__ __launch_bounds__(256) void conv2_kernel(
    const float* __restrict__ wl, const float* __restrict__ bl,
    const float* __restrict__ wr, const int* __restrict__ batch,
    int n, int ntiles)
{
    __shared__ __align__(16) float4 sw[64 * 32];   // 32KB
    __shared__ uint2 sAH[8][6][32];                // 12KB
    __shared__ int   s_idx[8][32];                 // 1KB

    for (int i = threadIdx.x; i < 64 * 32; i += blockDim.x) {
        int k = i >> 5, o2 = (i & 31) * 2;
        sw[i] = make_float4(wl[k * 64 + o2],     wr[k * 64 + o2],
                            wl[k * 64 + o2 + 1], wr[k * 64 + o2 + 1]);
    }
    __syncthreads();

    int warp = threadIdx.x >> 5, lane = threadIdx.x & 31;
    float bias0 = __ldg(&bl[2 * lane]), bias1 = __ldg(&bl[2 * lane + 1]);
    const unsigned* __restrict__ h1u = (const unsigned*)g_h1;

    for (int tile = blockIdx.x; tile < ntiles; tile += gridDim.x) {
        int nbase = tile * 48 + warp * 6;

        // ---- gather 6 nodes ----
        #pragma unroll
        for (int t = 0; t < 6; t++) {
            int node = nbase + t;
            if (node < n) {
                int s0 = g_rowptr[node], s1 = g_rowptr[node + 1];
                float ax = 0.f, ay = 0.f;
                for (int base = s0; base < s1; base += 32) {
                    int cnt = min(32, s1 - base);
                    __syncwarp();
                    if (base + lane < s1) s_idx[warp][lane] = g_src_sorted[base + lane];
                    __syncwarp();
                    int j = 0;
                    for (; j + 4 <= cnt; j += 4) {
                        int i0 = s_idx[warp][j],     i1 = s_idx[warp][j + 1];
                        int i2 = s_idx[warp][j + 2], i3 = s_idx[warp][j + 3];
                        float2 v0 = bf2f(h1u[i0 * 32 + lane]);
                        float2 v1 = bf2f(h1u[i1 * 32 + lane]);
                        float2 v2 = bf2f(h1u[i2 * 32 + lane]);
                        float2 v3 = bf2f(h1u[i3 * 32 + lane]);
                        ax += (v0.x + v1.x) + (v2.x + v3.x);
                        ay += (v0.y + v1.y) + (v2.y + v3.y);
                    }
                    for (; j < cnt; j++) {
                        float2 v = bf2f(h1u[s_idx[warp][j] * 32 + lane]);
                        ax += v.x; ay += v.y;
                    }
                }
                int deg = s1 - s0;
                float inv = (deg > 0) ? 1.f / (float)deg : 0.f;
                sAH[warp][t][lane] = make_uint2(f2bf(ax * inv, ay * inv),
                                                h1u[node * 32 + lane]);
            } else {
                sAH[warp][t][lane] = make_uint2(0u, 0u);
            }
        }
        __syncwarp();

        // ---- matmul: 6 nodes, out dims (2l, 2l+1) per lane ----
        float acc0[6], acc1[6];
        #pragma unroll
        for (int t = 0; t < 6; t++) { acc0[t] = bias0; acc1[t] = bias1; }
        #pragma unroll
        for (int kp = 0; kp < 32; kp++) {
            float4 w0 = sw[(2 * kp) * 32 + lane];
            float4 w1 = sw[(2 * kp + 1) * 32 + lane];
            #pragma unroll
            for (int t = 0; t < 6; t++) {
                uint2 v = sAH[warp][t][kp];
                float2 a = bf2f(v.x);
                float2 h = bf2f(v.y);
                acc0[t] += a.x * w0.x + h.x * w0.y + a.y * w1.x + h.y * w1.y;
                acc1[t] += a.x * w0.z + h.x * w0.w + a.y * w1.z + h.y * w1.w;
            }
        }

        // ---- L2 norm + relu + per-warp segmented pool flush ----
        float ss[6];
        #pragma unroll
        for (int t = 0; t < 6; t++) ss[t] = acc0[t] * acc0[t] + acc1[t] * acc1[t];
        #pragma unroll
        for (int off = 16; off; off >>= 1) {
            #pragma unroll
            for (int t = 0; t < 6; t++) ss[t] += __shfl_xor_sync(0xFFFFFFFFu, ss[t], off);
        }

        int bid[6];
        #pragma unroll
        for (int t = 0; t < 6; t++)
            bid[t] = (nbase + t < n) ? __ldg(&batch[nbase + t]) : -1;

        float p0 = 0.f, p1 = 0.f;
        int cur = -1;
        #pragma unroll
        for (int t = 0; t < 6; t++) {
            if (bid[t] < 0) break;
            float iv = 1.f / fmaxf(sqrtf(ss[t]), 1e-12f);
            float o0 = fmaxf(acc0[t] * iv, 0.f);
            float o1 = fmaxf(acc1[t] * iv, 0.f);
            if (bid[t] != cur) {
                if (cur >= 0) {
                    atomicAdd(&g_gsum[cur * 64 + 2 * lane],     p0);
                    atomicAdd(&g_gsum[cur * 64 + 2 * lane + 1], p1);
                }
                cur = bid[t]; p0 = 0.f; p1 = 0.f;
            }
            p0 += o0; p1 += o1;
        }
        if (cur >= 0) {
            atomicAdd(&g_gsum[cur * 64 + 2 * lane],     p0);
            atomicAdd(&g_gsum[cur * 64 + 2 * lane + 1], p1);
        }
    }
}

// ---------------- head MLP: 64 -> 64 -> 16 -> 1 ------------------------------
__global__ void head_kernel(const float* __restrict__ p1w, const float* __restrict__ p1b,
                            const float* __restrict__ p2w, const float* __restrict__ p2b,
                            const float* __restrict__ ow,  const float* __restrict__ ob,
                            float* __restrict__ out) {
    int g = blockIdx.x, t = threadIdx.x;  // 64 threads
    __shared__ float sg[64], s1[64], s2[16];
    float c = (float)g_gcnt[g];
    float invc = 1.f / fmaxf(c, 1.f);
    sg[t] = g_gsum[g * 64 + t] * invc;
    __syncthreads();
    float acc = __ldg(&p1b[t]);
    #pragma unroll 8
    for (int k = 0; k < 64; k++) acc += sg[k] * __ldg(&p1w[k * 64 + t]);
    s1[t] = fmaxf(acc, 0.f);
    __syncthreads();
    if (t < 16) {
        float a2 = __ldg(&p2b[t]);
        #pragma unroll 8
        for (int k = 0; k < 64; k++) a2 += s1[k] * __ldg(&p2w[k * 16 + t]);
        s2[t] = fmaxf(a2, 0.f);
    }
    __syncthreads();
    if (t == 0) {
        float o = __ldg(&ob[0]);
        #pragma unroll
        for (int k = 0; k < 16; k++) o += s2[k] * __ldg(&ow[k]);
        out[g] = o;
    }
}

// ---------------- launcher ---------------------------------------------------
extern "C" void kernel_launch(void* const* d_in, const int* in_sizes, int n_in,
                              void* d_out, int out_size) {
    const float* x     = (const float*)d_in[0];
    const int*   ei    = (const int*)d_in[1];
    const int*   batch = (const int*)d_in[2];
    const float* pre_w = (const float*)d_in[4];
    const float* pre_b = (const float*)d_in[5];
    const float* c1_wl = (const float*)d_in[6];
    const float* c1_bl = (const float*)d_in[7];
    const float* c1_wr = (const float*)d_in[8];
    const float* c2_wl = (const float*)d_in[9];
    const float* c2_bl = (const float*)d_in[10];
    const float* c2_wr = (const float*)d_in[11];
    const float* p1_w  = (const float*)d_in[12];
    const float* p1_b  = (const float*)d_in[13];
    const float* p2_w  = (const float*)d_in[14];
    const float* p2_b  = (const float*)d_in[15];
    const float* o_w   = (const float*)d_in[16];
    const float* o_b   = (const float*)d_in[17];

    int n = in_sizes[0] / 5;          // nodes
    int E = in_sizes[1] / 2;          // edges
    int G = out_size;                 // graphs
    const int* src = ei;
    const int* dst = ei + E;
    float* out = (float*)d_out;

    int nb = (n + 1023) / 1024;
    int nt1 = (n + 31) / 32;
    int nt2 = (n + 47) / 48;
    int c1_blocks = min(nt1, 148 * 8);
    int c2_blocks = min(nt2, 148 * 4);

    void *p_deg = nullptr, *p_gsum = nullptr, *p_gcnt = nullptr;
    cudaGetSymbolAddress(&p_deg, g_deg);
    cudaGetSymbolAddress(&p_gsum, g_gsum);
    cudaGetSymbolAddress(&p_gcnt, g_gcnt);
    cudaMemsetAsync(p_deg, 0, n * sizeof(int), 0);
    cudaMemsetAsync(p_gsum, 0, G * 64 * sizeof(float), 0);
    cudaMemsetAsync(p_gcnt, 0, G * sizeof(int), 0);

    degree_kernel<<<(max(E, n) + 255) / 256, 256>>>(dst, batch, E, n);
    scan1_kernel<<<nb, 1024>>>(n);
    scan2_kernel<<<1, 1024>>>(nb, n);
    scan3_kernel<<<(n + 255) / 256, 256>>>(n);
    bucket_kernel<<<(E + 255) / 256, 256>>>(src, dst, E);
    pre_kernel<<<(n * 32 + 255) / 256, 256>>>(x, pre_w, pre_b, n);
    conv1_kernel<<<c1_blocks, 256>>>(c1_wl, c1_bl, c1_wr, n, nt1);
    conv2_kernel<<<c2_blocks, 256>>>(c2_wl, c2_bl, c2_wr, batch, n, nt2);
    head_kernel<<<G, 64>>>(p1_w, p1_b, p2_w, p2_b, o_w, o_b, out);
}

// round 7
// speedup vs baseline: 1.0899x; 1.0899x over previous
#include <cuda_runtime.h>
#include <cuda_bf16.h>
#include <cstdint>

#define N_NODES_MAX 100000
#define N_EDGES_MAX 1600000
#define N_GRAPHS_MAX 512

// ---------------- scratch (device globals; no allocation allowed) ----------
__device__ __align__(16) __nv_bfloat16 g_h0[N_NODES_MAX * 32];
__device__ __align__(16) __nv_bfloat16 g_h1[N_NODES_MAX * 64];
__device__ int   g_deg[N_NODES_MAX];
__device__ int   g_rowptr[N_NODES_MAX + 1];
__device__ int   g_wp[N_NODES_MAX];
__device__ int   g_src_sorted[N_EDGES_MAX];
__device__ int   g_bsum[1024];
__device__ int   g_boff[1024];
__device__ __align__(16) float g_gsum[N_GRAPHS_MAX * 64];
__device__ int   g_gcnt[N_GRAPHS_MAX];

__device__ __forceinline__ float2 bf2f(unsigned u) {
    __nv_bfloat162 b;
    *(unsigned*)&b = u;
    return __bfloat1622float2(b);
}
__device__ __forceinline__ unsigned f2bf(float a, float b) {
    __nv_bfloat162 v = __floats2bfloat162_rn(a, b);
    return *(unsigned*)&v;
}

// ---------------- degree count + graph node count ----------------------------
__global__ void degree_kernel(const int* __restrict__ dst,
                              const int* __restrict__ batch, int E, int n) {
    int i = blockIdx.x * blockDim.x + threadIdx.x;
    if (i < E) atomicAdd(&g_deg[dst[i]], 1);
    if (i < n) atomicAdd(&g_gcnt[batch[i]], 1);
}

// ---------------- multi-block scan, pass 1 -----------------------------------
__global__ void scan1_kernel(int n) {
    __shared__ int warpsums[32];
    int t = threadIdx.x, lane = t & 31, w = t >> 5;
    int i = blockIdx.x * 1024 + t;
    int v = (i < n) ? g_deg[i] : 0;
    int x = v;
    #pragma unroll
    for (int off = 1; off < 32; off <<= 1) {
        int u = __shfl_up_sync(0xFFFFFFFFu, x, off);
        if (lane >= off) x += u;
    }
    if (lane == 31) warpsums[w] = x;
    __syncthreads();
    if (w == 0) {
        int y = warpsums[lane];
        #pragma unroll
        for (int off = 1; off < 32; off <<= 1) {
            int u = __shfl_up_sync(0xFFFFFFFFu, y, off);
            if (lane >= off) y += u;
        }
        warpsums[lane] = y;
    }
    __syncthreads();
    int woff = (w > 0) ? warpsums[w - 1] : 0;
    if (i < n) g_rowptr[i] = x + woff - v;
    if (t == 0) g_bsum[blockIdx.x] = warpsums[31];
}

// ---------------- scan pass 2 -------------------------------------------------
__global__ void scan2_kernel(int nb, int n) {
    __shared__ int warpsums[32];
    int t = threadIdx.x, lane = t & 31, w = t >> 5;
    int v = (t < nb) ? g_bsum[t] : 0;
    int x = v;
    #pragma unroll
    for (int off = 1; off < 32; off <<= 1) {
        int u = __shfl_up_sync(0xFFFFFFFFu, x, off);
        if (lane >= off) x += u;
    }
    if (lane == 31) warpsums[w] = x;
    __syncthreads();
    if (w == 0) {
        int y = warpsums[lane];
        #pragma unroll
        for (int off = 1; off < 32; off <<= 1) {
            int u = __shfl_up_sync(0xFFFFFFFFu, y, off);
            if (lane >= off) y += u;
        }
        warpsums[lane] = y;
    }
    __syncthreads();
    int woff = (w > 0) ? warpsums[w - 1] : 0;
    if (t < nb) g_boff[t] = x + woff - v;
    if (t == 0) g_rowptr[n] = warpsums[31];
}

// ---------------- scan pass 3 -------------------------------------------------
__global__ void scan3_kernel(int n) {
    int i = blockIdx.x * blockDim.x + threadIdx.x;
    if (i < n) {
        int v = g_rowptr[i] + g_boff[i >> 10];
        g_rowptr[i] = v;
        g_wp[i] = v;
    }
}

// ---------------- bucket edges by dst ----------------------------------------
__global__ void bucket_kernel(const int* __restrict__ src,
                              const int* __restrict__ dst, int E) {
    int e = blockIdx.x * blockDim.x + threadIdx.x;
    if (e < E) {
        int d = dst[e];
        int p = atomicAdd(&g_wp[d], 1);
        g_src_sorted[p] = src[e];
    }
}

// ---------------- pre MLP: x[N,5] @ W[5,32] + b, relu -> bf16 ----------------
__global__ void pre_kernel(const float* __restrict__ x,
                           const float* __restrict__ w,
                           const float* __restrict__ b, int n) {
    int tid = blockIdx.x * blockDim.x + threadIdx.x;
    if (tid >= n * 32) return;
    int node = tid >> 5, j = tid & 31;
    const float* xr = x + node * 5;
    float acc = __ldg(&b[j]);
    #pragma unroll
    for (int k = 0; k < 5; k++) acc += xr[k] * __ldg(&w[k * 32 + j]);
    g_h0[tid] = __float2bfloat16(fmaxf(acc, 0.f));
}

// ===== conv1: persistent, 4 nodes/warp, fp32 weights, direct gather =========
__global__ __launch_bounds__(256) void conv1_kernel(
    const float* __restrict__ wl, const float* __restrict__ bl,
    const float* __restrict__ wr, int n, int ntiles)
{
    __shared__ __align__(16) float4 sw[32 * 32];   // 16KB {wl[k][2l],wr[k][2l],wl[k][2l+1],wr[k][2l+1]}
    __shared__ float2 sA[8][4][32];                // 8KB (a, h)

    for (int i = threadIdx.x; i < 32 * 32; i += blockDim.x) {
        int k = i >> 5, o2 = (i & 31) * 2;
        sw[i] = make_float4(wl[k * 64 + o2],     wr[k * 64 + o2],
                            wl[k * 64 + o2 + 1], wr[k * 64 + o2 + 1]);
    }
    __syncthreads();

    int warp = threadIdx.x >> 5, lane = threadIdx.x & 31;
    float bias0 = __ldg(&bl[2 * lane]), bias1 = __ldg(&bl[2 * lane + 1]);

    for (int tile = blockIdx.x; tile < ntiles; tile += gridDim.x) {
        int nbase = tile * 32 + warp * 4;

        #pragma unroll
        for (int t = 0; t < 4; t++) {
            int node = nbase + t;
            float a = 0.f, h = 0.f;
            if (node < n) {
                int s0 = g_rowptr[node], s1 = g_rowptr[node + 1];
                int e = s0;
                for (; e + 4 <= s1; e += 4) {
                    int i0 = __ldg(&g_src_sorted[e]);
                    int i1 = __ldg(&g_src_sorted[e + 1]);
                    int i2 = __ldg(&g_src_sorted[e + 2]);
                    int i3 = __ldg(&g_src_sorted[e + 3]);
                    float v0 = __bfloat162float(g_h0[i0 * 32 + lane]);
                    float v1 = __bfloat162float(g_h0[i1 * 32 + lane]);
                    float v2 = __bfloat162float(g_h0[i2 * 32 + lane]);
                    float v3 = __bfloat162float(g_h0[i3 * 32 + lane]);
                    a += (v0 + v1) + (v2 + v3);
                }
                for (; e < s1; e++)
                    a += __bfloat162float(g_h0[__ldg(&g_src_sorted[e]) * 32 + lane]);
                int deg = s1 - s0;
                a *= (deg > 0) ? 1.f / (float)deg : 0.f;
                h = __bfloat162float(g_h0[node * 32 + lane]);
            }
            sA[warp][t][lane] = make_float2(a, h);
        }
        __syncwarp();

        float a00 = bias0, a01 = bias1, a10 = bias0, a11 = bias1;
        float a20 = bias0, a21 = bias1, a30 = bias0, a31 = bias1;
        #pragma unroll
        for (int k = 0; k < 32; k++) {
            float4 w = sw[k * 32 + lane];
            float2 A0 = sA[warp][0][k], A1 = sA[warp][1][k];
            float2 A2 = sA[warp][2][k], A3 = sA[warp][3][k];
            a00 += A0.x * w.x + A0.y * w.y;  a01 += A0.x * w.z + A0.y * w.w;
            a10 += A1.x * w.x + A1.y * w.y;  a11 += A1.x * w.z + A1.y * w.w;
            a20 += A2.x * w.x + A2.y * w.y;  a21 += A2.x * w.z + A2.y * w.w;
            a30 += A3.x * w.x + A3.y * w.y;  a31 += A3.x * w.z + A3.y * w.w;
        }

        float s0_ = a00 * a00 + a01 * a01;
        float s1_ = a10 * a10 + a11 * a11;
        float s2_ = a20 * a20 + a21 * a21;
        float s3_ = a30 * a30 + a31 * a31;
        #pragma unroll
        for (int off = 16; off; off >>= 1) {
            s0_ += __shfl_xor_sync(0xFFFFFFFFu, s0_, off);
            s1_ += __shfl_xor_sync(0xFFFFFFFFu, s1_, off);
            s2_ += __shfl_xor_sync(0xFFFFFFFFu, s2_, off);
            s3_ += __shfl_xor_sync(0xFFFFFFFFu, s3_, off);
        }
        float i0 = 1.f / fmaxf(sqrtf(s0_), 1e-12f);
        float i1 = 1.f / fmaxf(sqrtf(s1_), 1e-12f);
        float i2 = 1.f / fmaxf(sqrtf(s2_), 1e-12f);
        float i3 = 1.f / fmaxf(sqrtf(s3_), 1e-12f);
        unsigned* o = (unsigned*)g_h1;
        if (nbase + 0 < n) o[(nbase + 0) * 32 + lane] = f2bf(fmaxf(a00 * i0, 0.f), fmaxf(a01 * i0, 0.f));
        if (nbase + 1 < n) o[(nbase + 1) * 32 + lane] = f2bf(fmaxf(a10 * i1, 0.f), fmaxf(a11 * i1, 0.f));
        if (nbase + 2 < n) o[(nbase + 2) * 32 + lane] = f2bf(fmaxf(a20 * i2, 0.f), fmaxf(a21 * i2, 0.f));
        if (nbase + 3 < n) o[(nbase + 3) * 32 + lane] = f2bf(fmaxf(a30 * i3, 0.f), fmaxf(a31 * i3, 0.f));
    }
}

// ===== conv2 + fused pool: persistent, 4 nodes/warp, fp32 weights ===========
// staging: uint2 { bf16x2(ax,ay), raw bf16x2 H-bits }
__global__ __launch_bounds__(256) void conv2_kernel(
    const float* __restrict__ wl, const float* __restrict__ bl,
    const float* __restrict__ wr, const int* __restrict__ batch,
    int n, int ntiles)
{
    __shared__ __align__(16) float4 sw[64 * 32];   // 32KB
    __shared__ uint2 sAH[8][4][32];                // 8KB

    for (int i = threadIdx.x; i < 64 * 32; i += blockDim.x) {
        int k = i >> 5, o2 = (i & 31) * 2;
        sw[i] = make_float4(wl[k * 64 + o2],     wr[k * 64 + o2],
                            wl[k * 64 + o2 + 1], wr[k * 64 + o2 + 1]);
    }
    __syncthreads();

    int warp = threadIdx.x >> 5, lane = threadIdx.x & 31;
    float bias0 = __ldg(&bl[2 * lane]), bias1 = __ldg(&bl[2 * lane + 1]);
    const unsigned* __restrict__ h1u = (const unsigned*)g_h1;

    for (int tile = blockIdx.x; tile < ntiles; tile += gridDim.x) {
        int nbase = tile * 32 + warp * 4;

        // ---- gather 4 nodes (direct uniform index loads) ----
        #pragma unroll
        for (int t = 0; t < 4; t++) {
            int node = nbase + t;
            if (node < n) {
                int s0 = g_rowptr[node], s1 = g_rowptr[node + 1];
                float ax = 0.f, ay = 0.f;
                int e = s0;
                for (; e + 4 <= s1; e += 4) {
                    int i0 = __ldg(&g_src_sorted[e]);
                    int i1 = __ldg(&g_src_sorted[e + 1]);
                    int i2 = __ldg(&g_src_sorted[e + 2]);
                    int i3 = __ldg(&g_src_sorted[e + 3]);
                    float2 v0 = bf2f(h1u[i0 * 32 + lane]);
                    float2 v1 = bf2f(h1u[i1 * 32 + lane]);
                    float2 v2 = bf2f(h1u[i2 * 32 + lane]);
                    float2 v3 = bf2f(h1u[i3 * 32 + lane]);
                    ax += (v0.x + v1.x) + (v2.x + v3.x);
                    ay += (v0.y + v1.y) + (v2.y + v3.y);
                }
                for (; e < s1; e++) {
                    float2 v = bf2f(h1u[__ldg(&g_src_sorted[e]) * 32 + lane]);
                    ax += v.x; ay += v.y;
                }
                int deg = s1 - s0;
                float inv = (deg > 0) ? 1.f / (float)deg : 0.f;
                sAH[warp][t][lane] = make_uint2(f2bf(ax * inv, ay * inv),
                                                h1u[node * 32 + lane]);
            } else {
                sAH[warp][t][lane] = make_uint2(0u, 0u);
            }
        }
        __syncwarp();

        // ---- matmul: 4 nodes, out dims (2l, 2l+1) per lane ----
        float acc0[4], acc1[4];
        #pragma unroll
        for (int t = 0; t < 4; t++) { acc0[t] = bias0; acc1[t] = bias1; }
        #pragma unroll
        for (int kp = 0; kp < 32; kp++) {
            float4 w0 = sw[(2 * kp) * 32 + lane];
            float4 w1 = sw[(2 * kp + 1) * 32 + lane];
            #pragma unroll
            for (int t = 0; t < 4; t++) {
                uint2 v = sAH[warp][t][kp];
                float2 a = bf2f(v.x);
                float2 h = bf2f(v.y);
                acc0[t] += a.x * w0.x + h.x * w0.y + a.y * w1.x + h.y * w1.y;
                acc1[t] += a.x * w0.z + h.x * w0.w + a.y * w1.z + h.y * w1.w;
            }
        }

        // ---- L2 norm + relu + per-warp segmented pool flush ----
        float ss[4];
        #pragma unroll
        for (int t = 0; t < 4; t++) ss[t] = acc0[t] * acc0[t] + acc1[t] * acc1[t];
        #pragma unroll
        for (int off = 16; off; off >>= 1) {
            #pragma unroll
            for (int t = 0; t < 4; t++) ss[t] += __shfl_xor_sync(0xFFFFFFFFu, ss[t], off);
        }

        int bid[4];
        #pragma unroll
        for (int t = 0; t < 4; t++)
            bid[t] = (nbase + t < n) ? __ldg(&batch[nbase + t]) : -1;

        float p0 = 0.f, p1 = 0.f;
        int cur = -1;
        #pragma unroll
        for (int t = 0; t < 4; t++) {
            if (bid[t] < 0) break;
            float iv = 1.f / fmaxf(sqrtf(ss[t]), 1e-12f);
            float o0 = fmaxf(acc0[t] * iv, 0.f);
            float o1 = fmaxf(acc1[t] * iv, 0.f);
            if (bid[t] != cur) {
                if (cur >= 0) {
                    atomicAdd(&g_gsum[cur * 64 + 2 * lane],     p0);
                    atomicAdd(&g_gsum[cur * 64 + 2 * lane + 1], p1);
                }
                cur = bid[t]; p0 = 0.f; p1 = 0.f;
            }
            p0 += o0; p1 += o1;
        }
        if (cur >= 0) {
            atomicAdd(&g_gsum[cur * 64 + 2 * lane],     p0);
            atomicAdd(&g_gsum[cur * 64 + 2 * lane + 1], p1);
        }
    }
}

// ---------------- head MLP: 64 -> 64 -> 16 -> 1 ------------------------------
__global__ void head_kernel(const float* __restrict__ p1w, const float* __restrict__ p1b,
                            const float* __restrict__ p2w, const float* __restrict__ p2b,
                            const float* __restrict__ ow,  const float* __restrict__ ob,
                            float* __restrict__ out) {
    int g = blockIdx.x, t = threadIdx.x;  // 64 threads
    __shared__ float sg[64], s1[64], s2[16];
    float c = (float)g_gcnt[g];
    float invc = 1.f / fmaxf(c, 1.f);
    sg[t] = g_gsum[g * 64 + t] * invc;
    __syncthreads();
    float acc = __ldg(&p1b[t]);
    #pragma unroll 8
    for (int k = 0; k < 64; k++) acc += sg[k] * __ldg(&p1w[k * 64 + t]);
    s1[t] = fmaxf(acc, 0.f);
    __syncthreads();
    if (t < 16) {
        float a2 = __ldg(&p2b[t]);
        #pragma unroll 8
        for (int k = 0; k < 64; k++) a2 += s1[k] * __ldg(&p2w[k * 16 + t]);
        s2[t] = fmaxf(a2, 0.f);
    }
    __syncthreads();
    if (t == 0) {
        float o = __ldg(&ob[0]);
        #pragma unroll
        for (int k = 0; k < 16; k++) o += s2[k] * __ldg(&ow[k]);
        out[g] = o;
    }
}

// ---------------- launcher ---------------------------------------------------
extern "C" void kernel_launch(void* const* d_in, const int* in_sizes, int n_in,
                              void* d_out, int out_size) {
    const float* x     = (const float*)d_in[0];
    const int*   ei    = (const int*)d_in[1];
    const int*   batch = (const int*)d_in[2];
    const float* pre_w = (const float*)d_in[4];
    const float* pre_b = (const float*)d_in[5];
    const float* c1_wl = (const float*)d_in[6];
    const float* c1_bl = (const float*)d_in[7];
    const float* c1_wr = (const float*)d_in[8];
    const float* c2_wl = (const float*)d_in[9];
    const float* c2_bl = (const float*)d_in[10];
    const float* c2_wr = (const float*)d_in[11];
    const float* p1_w  = (const float*)d_in[12];
    const float* p1_b  = (const float*)d_in[13];
    const float* p2_w  = (const float*)d_in[14];
    const float* p2_b  = (const float*)d_in[15];
    const float* o_w   = (const float*)d_in[16];
    const float* o_b   = (const float*)d_in[17];

    int n = in_sizes[0] / 5;          // nodes
    int E = in_sizes[1] / 2;          // edges
    int G = out_size;                 // graphs
    const int* src = ei;
    const int* dst = ei + E;
    float* out = (float*)d_out;

    int nb = (n + 1023) / 1024;
    int ntiles = (n + 31) / 32;
    int c1_blocks = min(ntiles, 148 * 8);
    int c2_blocks = min(ntiles, 148 * 5);

    void *p_deg = nullptr, *p_gsum = nullptr, *p_gcnt = nullptr;
    cudaGetSymbolAddress(&p_deg, g_deg);
    cudaGetSymbolAddress(&p_gsum, g_gsum);
    cudaGetSymbolAddress(&p_gcnt, g_gcnt);
    cudaMemsetAsync(p_deg, 0, n * sizeof(int), 0);
    cudaMemsetAsync(p_gsum, 0, G * 64 * sizeof(float), 0);
    cudaMemsetAsync(p_gcnt, 0, G * sizeof(int), 0);

    degree_kernel<<<(max(E, n) + 255) / 256, 256>>>(dst, batch, E, n);
    scan1_kernel<<<nb, 1024>>>(n);
    scan2_kernel<<<1, 1024>>>(nb, n);
    scan3_kernel<<<(n + 255) / 256, 256>>>(n);
    bucket_kernel<<<(E + 255) / 256, 256>>>(src, dst, E);
    pre_kernel<<<(n * 32 + 255) / 256, 256>>>(x, pre_w, pre_b, n);
    conv1_kernel<<<c1_blocks, 256>>>(c1_wl, c1_bl, c1_wr, n, ntiles);
    conv2_kernel<<<c2_blocks, 256>>>(c2_wl, c2_bl, c2_wr, batch, n, ntiles);
    head_kernel<<<G, 64>>>(p1_w, p1_b, p2_w, p2_b, o_w, o_b, out);
}

// round 8
// speedup vs baseline: 1.1798x; 1.0825x over previous
#include <cuda_runtime.h>
#include <cuda_bf16.h>
#include <cstdint>

#define N_NODES_MAX 100000
#define N_EDGES_MAX 1600000
#define N_GRAPHS_MAX 512

// ---------------- scratch (device globals; no allocation allowed) ----------
__device__ __align__(16) __nv_bfloat16 g_h0[N_NODES_MAX * 32];
__device__ __align__(16) __nv_bfloat16 g_agg1[N_NODES_MAX * 32];
__device__ __align__(16) __nv_bfloat16 g_h1[N_NODES_MAX * 64];
__device__ __align__(16) __nv_bfloat16 g_agg2[N_NODES_MAX * 64];
__device__ int   g_deg[N_NODES_MAX];
__device__ int   g_rowptr[N_NODES_MAX + 1];
__device__ int   g_wp[N_NODES_MAX];
__device__ int   g_src_sorted[N_EDGES_MAX];
__device__ int   g_bsum[1024];
__device__ int   g_boff[1024];
__device__ __align__(16) float g_gsum[N_GRAPHS_MAX * 64];
__device__ int   g_gcnt[N_GRAPHS_MAX];

__device__ __forceinline__ float2 bf2f(unsigned u) {
    __nv_bfloat162 b;
    *(unsigned*)&b = u;
    return __bfloat1622float2(b);
}
__device__ __forceinline__ unsigned f2bf(float a, float b) {
    __nv_bfloat162 v = __floats2bfloat162_rn(a, b);
    return *(unsigned*)&v;
}
// ---- packed f32x2 helpers (Blackwell FFMA2) ----
__device__ __forceinline__ unsigned long long pk2(float x, float y) {
    unsigned long long r;
    asm("mov.b64 %0, {%1, %2};" : "=l"(r) : "f"(x), "f"(y));
    return r;
}
__device__ __forceinline__ void upk2(unsigned long long v, float& x, float& y) {
    asm("mov.b64 {%0, %1}, %2;" : "=f"(x), "=f"(y) : "l"(v));
}
__device__ __forceinline__ void fma2(unsigned long long& d,
                                     unsigned long long a, unsigned long long b) {
    asm("fma.rn.f32x2 %0, %1, %2, %0;" : "+l"(d) : "l"(a), "l"(b));
}

// ---------------- degree count + graph node count ----------------------------
__global__ void degree_kernel(const int* __restrict__ dst,
                              const int* __restrict__ batch, int E, int n) {
    int i = blockIdx.x * blockDim.x + threadIdx.x;
    if (i < E) atomicAdd(&g_deg[dst[i]], 1);
    if (i < n) atomicAdd(&g_gcnt[batch[i]], 1);
}

// ---------------- multi-block scan, pass 1 -----------------------------------
__global__ void scan1_kernel(int n) {
    __shared__ int warpsums[32];
    int t = threadIdx.x, lane = t & 31, w = t >> 5;
    int i = blockIdx.x * 1024 + t;
    int v = (i < n) ? g_deg[i] : 0;
    int x = v;
    #pragma unroll
    for (int off = 1; off < 32; off <<= 1) {
        int u = __shfl_up_sync(0xFFFFFFFFu, x, off);
        if (lane >= off) x += u;
    }
    if (lane == 31) warpsums[w] = x;
    __syncthreads();
    if (w == 0) {
        int y = warpsums[lane];
        #pragma unroll
        for (int off = 1; off < 32; off <<= 1) {
            int u = __shfl_up_sync(0xFFFFFFFFu, y, off);
            if (lane >= off) y += u;
        }
        warpsums[lane] = y;
    }
    __syncthreads();
    int woff = (w > 0) ? warpsums[w - 1] : 0;
    if (i < n) g_rowptr[i] = x + woff - v;
    if (t == 0) g_bsum[blockIdx.x] = warpsums[31];
}

// ---------------- scan pass 2 -------------------------------------------------
__global__ void scan2_kernel(int nb, int n) {
    __shared__ int warpsums[32];
    int t = threadIdx.x, lane = t & 31, w = t >> 5;
    int v = (t < nb) ? g_bsum[t] : 0;
    int x = v;
    #pragma unroll
    for (int off = 1; off < 32; off <<= 1) {
        int u = __shfl_up_sync(0xFFFFFFFFu, x, off);
        if (lane >= off) x += u;
    }
    if (lane == 31) warpsums[w] = x;
    __syncthreads();
    if (w == 0) {
        int y = warpsums[lane];
        #pragma unroll
        for (int off = 1; off < 32; off <<= 1) {
            int u = __shfl_up_sync(0xFFFFFFFFu, y, off);
            if (lane >= off) y += u;
        }
        warpsums[lane] = y;
    }
    __syncthreads();
    int woff = (w > 0) ? warpsums[w - 1] : 0;
    if (t < nb) g_boff[t] = x + woff - v;
    if (t == 0) g_rowptr[n] = warpsums[31];
}

// ---------------- scan pass 3 -------------------------------------------------
__global__ void scan3_kernel(int n) {
    int i = blockIdx.x * blockDim.x + threadIdx.x;
    if (i < n) {
        int v = g_rowptr[i] + g_boff[i >> 10];
        g_rowptr[i] = v;
        g_wp[i] = v;
    }
}

// ---------------- bucket edges by dst ----------------------------------------
__global__ void bucket_kernel(const int* __restrict__ src,
                              const int* __restrict__ dst, int E) {
    int e = blockIdx.x * blockDim.x + threadIdx.x;
    if (e < E) {
        int d = dst[e];
        int p = atomicAdd(&g_wp[d], 1);
        g_src_sorted[p] = src[e];
    }
}

// ---------------- pre MLP: x[N,5] @ W[5,32] + b, relu -> bf16 ----------------
__global__ void pre_kernel(const float* __restrict__ x,
                           const float* __restrict__ w,
                           const float* __restrict__ b, int n) {
    int tid = blockIdx.x * blockDim.x + threadIdx.x;
    if (tid >= n * 32) return;
    int node = tid >> 5, j = tid & 31;
    const float* xr = x + node * 5;
    float acc = __ldg(&b[j]);
    #pragma unroll
    for (int k = 0; k < 5; k++) acc += xr[k] * __ldg(&w[k * 32 + j]);
    g_h0[tid] = __float2bfloat16(fmaxf(acc, 0.f));
}

// ---------------- gather1: one node per warp, h0 -> agg1 (mean) --------------
__global__ __launch_bounds__(256) void gather1_kernel(int n) {
    int warp = (blockIdx.x * blockDim.x + threadIdx.x) >> 5;
    int lane = threadIdx.x & 31;
    if (warp >= n) return;
    int node = warp;
    int s0 = g_rowptr[node], s1 = g_rowptr[node + 1];
    float a = 0.f;
    int e = s0;
    for (; e + 4 <= s1; e += 4) {
        int i0 = __ldg(&g_src_sorted[e]);
        int i1 = __ldg(&g_src_sorted[e + 1]);
        int i2 = __ldg(&g_src_sorted[e + 2]);
        int i3 = __ldg(&g_src_sorted[e + 3]);
        float v0 = __bfloat162float(g_h0[i0 * 32 + lane]);
        float v1 = __bfloat162float(g_h0[i1 * 32 + lane]);
        float v2 = __bfloat162float(g_h0[i2 * 32 + lane]);
        float v3 = __bfloat162float(g_h0[i3 * 32 + lane]);
        a += (v0 + v1) + (v2 + v3);
    }
    for (; e < s1; e++)
        a += __bfloat162float(g_h0[__ldg(&g_src_sorted[e]) * 32 + lane]);
    int deg = s1 - s0;
    a *= (deg > 0) ? 1.f / (float)deg : 0.f;
    g_agg1[node * 32 + lane] = __float2bfloat16(a);
}

// ---------------- gather2: one node per warp, h1 -> agg2 (mean) --------------
__global__ __launch_bounds__(256) void gather2_kernel(int n) {
    int warp = (blockIdx.x * blockDim.x + threadIdx.x) >> 5;
    int lane = threadIdx.x & 31;
    if (warp >= n) return;
    int node = warp;
    const unsigned* __restrict__ h1u = (const unsigned*)g_h1;
    int s0 = g_rowptr[node], s1 = g_rowptr[node + 1];
    float ax = 0.f, ay = 0.f;
    int e = s0;
    for (; e + 4 <= s1; e += 4) {
        int i0 = __ldg(&g_src_sorted[e]);
        int i1 = __ldg(&g_src_sorted[e + 1]);
        int i2 = __ldg(&g_src_sorted[e + 2]);
        int i3 = __ldg(&g_src_sorted[e + 3]);
        float2 v0 = bf2f(h1u[i0 * 32 + lane]);
        float2 v1 = bf2f(h1u[i1 * 32 + lane]);
        float2 v2 = bf2f(h1u[i2 * 32 + lane]);
        float2 v3 = bf2f(h1u[i3 * 32 + lane]);
        ax += (v0.x + v1.x) + (v2.x + v3.x);
        ay += (v0.y + v1.y) + (v2.y + v3.y);
    }
    for (; e < s1; e++) {
        float2 v = bf2f(h1u[__ldg(&g_src_sorted[e]) * 32 + lane]);
        ax += v.x; ay += v.y;
    }
    int deg = s1 - s0;
    float inv = (deg > 0) ? 1.f / (float)deg : 0.f;
    ((unsigned*)g_agg2)[node * 32 + lane] = f2bf(ax * inv, ay * inv);
}

// ====== matmul1: (agg1|h0)[N,64] @ W -> h1, f32x2 FMA, 8 nodes/warp ==========
// weights: per (k,lane): ull2 { pk(wl[k][2l],wl[k][2l+1]), pk(wr[k][2l],wr[k][2l+1]) }
// staging: per (warp,t,k): ull2 { pk(a,a), pk(h,h) }
__global__ __launch_bounds__(256) void matmul1_kernel(
    const float* __restrict__ wl, const float* __restrict__ bl,
    const float* __restrict__ wr, int n)
{
    __shared__ __align__(16) ulonglong2 swp[32 * 32];     // 16KB
    __shared__ __align__(16) ulonglong2 sdup[8][8][32];   // 32KB

    for (int i = threadIdx.x; i < 32 * 32; i += blockDim.x) {
        int k = i >> 5, o2 = (i & 31) * 2;
        swp[i].x = pk2(wl[k * 64 + o2], wl[k * 64 + o2 + 1]);
        swp[i].y = pk2(wr[k * 64 + o2], wr[k * 64 + o2 + 1]);
    }
    __syncthreads();

    int warp = threadIdx.x >> 5, lane = threadIdx.x & 31;
    int nbase = blockIdx.x * 64 + warp * 8;
    unsigned long long bias = pk2(__ldg(&bl[2 * lane]), __ldg(&bl[2 * lane + 1]));

    // ---- stage: lane = k index ----
    #pragma unroll
    for (int t = 0; t < 8; t++) {
        int node = nbase + t;
        float a = 0.f, h = 0.f;
        if (node < n) {
            a = __bfloat162float(g_agg1[node * 32 + lane]);
            h = __bfloat162float(g_h0[node * 32 + lane]);
        }
        sdup[warp][t][lane].x = pk2(a, a);
        sdup[warp][t][lane].y = pk2(h, h);
    }
    __syncwarp();

    unsigned long long acc[8];
    #pragma unroll
    for (int t = 0; t < 8; t++) acc[t] = bias;

    #pragma unroll 4
    for (int k = 0; k < 32; k++) {
        ulonglong2 w = swp[k * 32 + lane];
        #pragma unroll
        for (int t = 0; t < 8; t++) {
            ulonglong2 d = sdup[warp][t][k];
            fma2(acc[t], d.x, w.x);
            fma2(acc[t], d.y, w.y);
        }
    }

    // ---- L2 norm + relu + store bf16 ----
    float o0[8], o1[8], ss[8];
    #pragma unroll
    for (int t = 0; t < 8; t++) {
        upk2(acc[t], o0[t], o1[t]);
        ss[t] = o0[t] * o0[t] + o1[t] * o1[t];
    }
    #pragma unroll
    for (int off = 16; off; off >>= 1) {
        #pragma unroll
        for (int t = 0; t < 8; t++) ss[t] += __shfl_xor_sync(0xFFFFFFFFu, ss[t], off);
    }
    unsigned* out = (unsigned*)g_h1;
    #pragma unroll
    for (int t = 0; t < 8; t++) {
        int node = nbase + t;
        if (node < n) {
            float iv = 1.f / fmaxf(sqrtf(ss[t]), 1e-12f);
            out[node * 32 + lane] = f2bf(fmaxf(o0[t] * iv, 0.f), fmaxf(o1[t] * iv, 0.f));
        }
    }
}

// === matmul2 + pool: (agg2|h1)[N,128] @ W -> pooled, f32x2, 8 nodes/warp =====
// k chunked in 2 passes of 32 to bound staging smem.
__global__ __launch_bounds__(256) void matmul2_kernel(
    const float* __restrict__ wl, const float* __restrict__ bl,
    const float* __restrict__ wr, const int* __restrict__ batch, int n)
{
    __shared__ __align__(16) ulonglong2 swp[64 * 32];     // 32KB
    __shared__ __align__(16) ulonglong2 sdup[8][8][32];   // 32KB (one chunk)

    for (int i = threadIdx.x; i < 64 * 32; i += blockDim.x) {
        int k = i >> 5, o2 = (i & 31) * 2;
        swp[i].x = pk2(wl[k * 64 + o2], wl[k * 64 + o2 + 1]);
        swp[i].y = pk2(wr[k * 64 + o2], wr[k * 64 + o2 + 1]);
    }
    __syncthreads();

    int warp = threadIdx.x >> 5, lane = threadIdx.x & 31;
    int nbase = blockIdx.x * 64 + warp * 8;
    unsigned long long bias = pk2(__ldg(&bl[2 * lane]), __ldg(&bl[2 * lane + 1]));

    unsigned long long acc[8];
    #pragma unroll
    for (int t = 0; t < 8; t++) acc[t] = bias;

    #pragma unroll
    for (int c = 0; c < 2; c++) {
        // ---- stage chunk c: lane = local k ----
        int ko = c * 32 + lane;
        #pragma unroll
        for (int t = 0; t < 8; t++) {
            int node = nbase + t;
            float a = 0.f, h = 0.f;
            if (node < n) {
                a = __bfloat162float(g_agg2[node * 64 + ko]);
                h = __bfloat162float(g_h1[node * 64 + ko]);
            }
            sdup[warp][t][lane].x = pk2(a, a);
            sdup[warp][t][lane].y = pk2(h, h);
        }
        __syncwarp();

        #pragma unroll 4
        for (int k = 0; k < 32; k++) {
            ulonglong2 w = swp[(c * 32 + k) * 32 + lane];
            #pragma unroll
            for (int t = 0; t < 8; t++) {
                ulonglong2 d = sdup[warp][t][k];
                fma2(acc[t], d.x, w.x);
                fma2(acc[t], d.y, w.y);
            }
        }
        __syncwarp();
    }

    // ---- L2 norm + relu + per-warp segmented pool flush ----
    float o0[8], o1[8], ss[8];
    #pragma unroll
    for (int t = 0; t < 8; t++) {
        upk2(acc[t], o0[t], o1[t]);
        ss[t] = o0[t] * o0[t] + o1[t] * o1[t];
    }
    #pragma unroll
    for (int off = 16; off; off >>= 1) {
        #pragma unroll
        for (int t = 0; t < 8; t++) ss[t] += __shfl_xor_sync(0xFFFFFFFFu, ss[t], off);
    }

    float p0 = 0.f, p1 = 0.f;
    int cur = -1;
    #pragma unroll
    for (int t = 0; t < 8; t++) {
        int node = nbase + t;
        if (node >= n) break;
        int b = __ldg(&batch[node]);
        float iv = 1.f / fmaxf(sqrtf(ss[t]), 1e-12f);
        float v0 = fmaxf(o0[t] * iv, 0.f);
        float v1 = fmaxf(o1[t] * iv, 0.f);
        if (b != cur) {
            if (cur >= 0) {
                atomicAdd(&g_gsum[cur * 64 + 2 * lane],     p0);
                atomicAdd(&g_gsum[cur * 64 + 2 * lane + 1], p1);
            }
            cur = b; p0 = 0.f; p1 = 0.f;
        }
        p0 += v0; p1 += v1;
    }
    if (cur >= 0) {
        atomicAdd(&g_gsum[cur * 64 + 2 * lane],     p0);
        atomicAdd(&g_gsum[cur * 64 + 2 * lane + 1], p1);
    }
}

// ---------------- head MLP: 64 -> 64 -> 16 -> 1 ------------------------------
__global__ void head_kernel(const float* __restrict__ p1w, const float* __restrict__ p1b,
                            const float* __restrict__ p2w, const float* __restrict__ p2b,
                            const float* __restrict__ ow,  const float* __restrict__ ob,
                            float* __restrict__ out) {
    int g = blockIdx.x, t = threadIdx.x;  // 64 threads
    __shared__ float sg[64], s1[64], s2[16];
    float c = (float)g_gcnt[g];
    float invc = 1.f / fmaxf(c, 1.f);
    sg[t] = g_gsum[g * 64 + t] * invc;
    __syncthreads();
    float acc = __ldg(&p1b[t]);
    #pragma unroll 8
    for (int k = 0; k < 64; k++) acc += sg[k] * __ldg(&p1w[k * 64 + t]);
    s1[t] = fmaxf(acc, 0.f);
    __syncthreads();
    if (t < 16) {
        float a2 = __ldg(&p2b[t]);
        #pragma unroll 8
        for (int k = 0; k < 64; k++) a2 += s1[k] * __ldg(&p2w[k * 16 + t]);
        s2[t] = fmaxf(a2, 0.f);
    }
    __syncthreads();
    if (t == 0) {
        float o = __ldg(&ob[0]);
        #pragma unroll
        for (int k = 0; k < 16; k++) o += s2[k] * __ldg(&ow[k]);
        out[g] = o;
    }
}

// ---------------- launcher ---------------------------------------------------
extern "C" void kernel_launch(void* const* d_in, const int* in_sizes, int n_in,
                              void* d_out, int out_size) {
    const float* x     = (const float*)d_in[0];
    const int*   ei    = (const int*)d_in[1];
    const int*   batch = (const int*)d_in[2];
    const float* pre_w = (const float*)d_in[4];
    const float* pre_b = (const float*)d_in[5];
    const float* c1_wl = (const float*)d_in[6];
    const float* c1_bl = (const float*)d_in[7];
    const float* c1_wr = (const float*)d_in[8];
    const float* c2_wl = (const float*)d_in[9];
    const float* c2_bl = (const float*)d_in[10];
    const float* c2_wr = (const float*)d_in[11];
    const float* p1_w  = (const float*)d_in[12];
    const float* p1_b  = (const float*)d_in[13];
    const float* p2_w  = (const float*)d_in[14];
    const float* p2_b  = (const float*)d_in[15];
    const float* o_w   = (const float*)d_in[16];
    const float* o_b   = (const float*)d_in[17];

    int n = in_sizes[0] / 5;          // nodes
    int E = in_sizes[1] / 2;          // edges
    int G = out_size;                 // graphs
    const int* src = ei;
    const int* dst = ei + E;
    float* out = (float*)d_out;

    int nb = (n + 1023) / 1024;

    void *p_deg = nullptr, *p_gsum = nullptr, *p_gcnt = nullptr;
    cudaGetSymbolAddress(&p_deg, g_deg);
    cudaGetSymbolAddress(&p_gsum, g_gsum);
    cudaGetSymbolAddress(&p_gcnt, g_gcnt);
    cudaMemsetAsync(p_deg, 0, n * sizeof(int), 0);
    cudaMemsetAsync(p_gsum, 0, G * 64 * sizeof(float), 0);
    cudaMemsetAsync(p_gcnt, 0, G * sizeof(int), 0);

    degree_kernel<<<(max(E, n) + 255) / 256, 256>>>(dst, batch, E, n);
    scan1_kernel<<<nb, 1024>>>(n);
    scan2_kernel<<<1, 1024>>>(nb, n);
    scan3_kernel<<<(n + 255) / 256, 256>>>(n);
    bucket_kernel<<<(E + 255) / 256, 256>>>(src, dst, E);
    pre_kernel<<<(n * 32 + 255) / 256, 256>>>(x, pre_w, pre_b, n);
    gather1_kernel<<<(n + 7) / 8, 256>>>(n);
    matmul1_kernel<<<(n + 63) / 64, 256>>>(c1_wl, c1_bl, c1_wr, n);
    gather2_kernel<<<(n + 7) / 8, 256>>>(n);
    matmul2_kernel<<<(n + 63) / 64, 256>>>(c2_wl, c2_bl, c2_wr, batch, n);
    head_kernel<<<G, 64>>>(p1_w, p1_b, p2_w, p2_b, o_w, o_b, out);
}